// round 10
// baseline (speedup 1.0000x reference)
#include <cuda_runtime.h>
#include <cuda_fp16.h>
#include <math.h>

#define NSC 7
#define NB 8
#define ADIM 512
#define MAPSZ (NB * ADIM * ADIM)       // 2,097,152 cells per scale
#define TTY 258                        // tile-row stride (even for uint4)
#define TTX 257                        // tile rows
#define MAPH (TTX * TTY)               // 66306 tiles (8B each) per (map, replica)
#define SC_U4 (4 * NB * MAPH / 2)      // uint4 count per scale's replicas

// Scratch: 4 shift-replicas per scale; each 2x2 logical tile = 4 x f16 = uint2.
// ~119 MB. INVARIANT: all-zero at entry to every kernel_launch call
// (__device__ globals zero-init at load; k_restore re-zeroes after use).
__device__ __align__(16) uint2 g_rep[NSC][4][NB * MAPH];
__device__ float        g_sumlog[NSC];
__device__ unsigned int g_max[NSC];     // float bits (values >= 0)
__device__ unsigned int g_nzero[NSC];
__device__ unsigned int g_npos;

// ---------------------------------------------------------------------------
// K1: bilinear scatter for scales [s0, s0+ns) — ONE red.global.add.noftz
// .v2.f16x2 per point. Replica (sx,sy) stores logical (x,y) at (x+sx, y+sy);
// sx=ixf&1, sy=iyf&1 puts the 2x2 footprint in exactly one aligned tile.
// Tile halves [0..3] = (dx,dy) = (0,0),(0,1),(1,0),(1,1).
// ---------------------------------------------------------------------------
__device__ __forceinline__ void scat1(int s, int b, float r, float c) {
    float xf = fminf(fmaxf(floorf(r), 0.f), 511.f);
    float yf = fminf(fmaxf(floorf(c), 0.f), 511.f);
    float xw = r - xf;
    float yw = c - yf;
    int ix = (int)xf, iy = (int)yf;
    int sx = ix & 1, sy = iy & 1;
    uint2* a = &g_rep[s][sx * 2 + sy][b * MAPH + ((ix + sx) >> 1) * TTY + ((iy + sy) >> 1)];
    float wx0 = 1.f - xw, wy0 = 1.f - yw;
    __half2 lo = __floats2half2_rn(wx0 * wy0, wx0 * yw);   // (0,0),(0,1)
    __half2 hi = __floats2half2_rn(xw * wy0,  xw * yw);    // (1,0),(1,1)
    unsigned ulo = *reinterpret_cast<unsigned*>(&lo);
    unsigned uhi = *reinterpret_cast<unsigned*>(&hi);
    asm volatile("red.global.add.noftz.v2.f16x2 [%0], {%1, %2};"
                 :: "l"(a), "r"(ulo), "r"(uhi)
                 : "memory");
}

__global__ void __launch_bounds__(256) k_scatter(
        const float4* __restrict__ r3, const float4* __restrict__ c3,
        const float4* __restrict__ r4, const float4* __restrict__ c4,
        int s0, int npts4) {
    int i = blockIdx.x * blockDim.x + threadIdx.x;   // [0, ns*MAPSZ/4)
    if (i >= npts4) return;
    int gi = s0 * (MAPSZ / 4) + i;                   // global coord index
    int s = s0 + (i >> 19);                          // scale (MAPSZ/4 = 2^19)
    int b = (i >> 16) & 7;                           // batch within scale

    float4 rA = r3[gi], cA = c3[gi];
    float4 rB = r4[gi], cB = c4[gi];
    scat1(s, b, rA.x, cA.x); scat1(s, b, rA.y, cA.y);
    scat1(s, b, rA.z, cA.z); scat1(s, b, rA.w, cA.w);
    scat1(s, b, rB.x, cB.x); scat1(s, b, rB.y, cB.y);
    scat1(s, b, rB.z, cB.z); scat1(s, b, rB.w, cB.w);
}

// ---------------------------------------------------------------------------
// K2: fused combine + max + masked log-stats for scales [s0, s0+ns).
// Each thread: TWO adjacent home tiles (8 logical cells), uint4 loads.
// BCE algebra: sum_{mask} min(lm - log(dm), 100)
//   = (npos - nzero)*lm - sum_{mask,dm>0} log(dm) + 100*nzero
// ---------------------------------------------------------------------------
__device__ __forceinline__ float lohalf(unsigned u) { return __half2float(__ushort_as_half((unsigned short)(u & 0xFFFF))); }
__device__ __forceinline__ float hihalf(unsigned u) { return __half2float(__ushort_as_half((unsigned short)(u >> 16))); }

__device__ __forceinline__ void stat_cell(float d, float t, float& sl,
                                          unsigned& nz, unsigned& np) {
    if (t == 1.0f) {
        np++;
        if (d == 0.f) nz++;
        else sl += logf(d);
    }
}

__global__ void __launch_bounds__(256) k_stats(const float* __restrict__ target, int s0) {
    int gid = blockIdx.x * blockDim.x + threadIdx.x;  // [0, ns * 2^18)
    const int s   = s0 + (gid >> 18);
    const int rem = gid & ((1 << 18) - 1);
    float mx = 0.f, sl = 0.f;
    unsigned nz = 0, np = 0;
    {
        int b   = rem >> 15;
        int bx  = (rem >> 7) & 255;
        int by  = (rem & 127) * 2;                   // even home-tile column
        int t00 = b * MAPH + bx * TTY + by;          // 16B aligned

        const uint2* __restrict__ r00 = g_rep[s][0];
        const uint2* __restrict__ r01 = g_rep[s][1];
        const uint2* __restrict__ r10 = g_rep[s][2];
        const uint2* __restrict__ r11 = g_rep[s][3];

        uint4 A  = *(const uint4*)(r00 + t00);
        uint4 B0 = *(const uint4*)(r01 + t00);
        uint2 B2 = r01[t00 + 2];
        uint4 C0 = *(const uint4*)(r10 + t00);
        uint4 C1 = *(const uint4*)(r10 + t00 + TTY);
        uint4 D0 = *(const uint4*)(r11 + t00);
        uint2 D2 = r11[t00 + 2];
        uint4 D1 = *(const uint4*)(r11 + t00 + TTY);
        uint2 D3 = r11[t00 + TTY + 2];

        // home tile 0: logical block (bx, by)
        float a00 = lohalf(A.x) + hihalf(B0.x) + lohalf(C0.y) + hihalf(D0.y);
        float a01 = hihalf(A.x) + lohalf(B0.z) + hihalf(C0.y) + lohalf(D0.w);
        float a10 = lohalf(A.y) + hihalf(B0.y) + lohalf(C1.x) + hihalf(D1.x);
        float a11 = hihalf(A.y) + lohalf(B0.w) + hihalf(C1.x) + lohalf(D1.z);
        // home tile 1: logical block (bx, by+1)
        float e00 = lohalf(A.z) + hihalf(B0.z) + lohalf(C0.w) + hihalf(D0.w);
        float e01 = hihalf(A.z) + lohalf(B2.x) + hihalf(C0.w) + lohalf(D2.y);
        float e10 = lohalf(A.w) + hihalf(B0.w) + lohalf(C1.z) + hihalf(D1.z);
        float e11 = hihalf(A.w) + lohalf(B2.y) + hihalf(C1.z) + lohalf(D3.x);

        mx = fmaxf(fmaxf(fmaxf(a00, a01), fmaxf(a10, a11)),
                   fmaxf(fmaxf(e00, e01), fmaxf(e10, e11)));

        const float* tp = target + b * (ADIM * ADIM) + (2 * bx) * ADIM + 2 * by;
        float4 t0 = *(const float4*)tp;
        float4 t1 = *(const float4*)(tp + ADIM);
        stat_cell(a00, t0.x, sl, nz, np);
        stat_cell(a01, t0.y, sl, nz, np);
        stat_cell(e00, t0.z, sl, nz, np);
        stat_cell(e01, t0.w, sl, nz, np);
        stat_cell(a10, t1.x, sl, nz, np);
        stat_cell(a11, t1.y, sl, nz, np);
        stat_cell(e10, t1.z, sl, nz, np);
        stat_cell(e11, t1.w, sl, nz, np);
    }
    #pragma unroll
    for (int o = 16; o; o >>= 1) {
        mx = fmaxf(mx, __shfl_xor_sync(0xFFFFFFFFu, mx, o));
        sl += __shfl_xor_sync(0xFFFFFFFFu, sl, o);
        nz += __shfl_xor_sync(0xFFFFFFFFu, nz, o);
        np += __shfl_xor_sync(0xFFFFFFFFu, np, o);
    }
    __shared__ float    smx[8], ssl[8];
    __shared__ unsigned snz[8], snp[8];
    int w = threadIdx.x >> 5;
    if ((threadIdx.x & 31) == 0) { smx[w] = mx; ssl[w] = sl; snz[w] = nz; snp[w] = np; }
    __syncthreads();
    if (threadIdx.x == 0) {   // whole CTA shares one s
        float bmx = smx[0], bsl = ssl[0];
        unsigned bnz = snz[0], bnp = snp[0];
        #pragma unroll
        for (int k = 1; k < 8; k++) {
            bmx = fmaxf(bmx, smx[k]); bsl += ssl[k]; bnz += snz[k]; bnp += snp[k];
        }
        atomicMax(&g_max[s], __float_as_uint(bmx));
        atomicAdd(&g_sumlog[s], bsl);
        if (bnz) atomicAdd(&g_nzero[s], bnz);
        if (s == 0) atomicAdd(&g_npos, bnp);
    }
}

// ---------------------------------------------------------------------------
// K3: restore scales [s0, s0+ns) replicas to zero (lines are L2-hot from the
// preceding stats). If do_final != 0, block 0 / thread 0 also computes the
// loss (all stats kernels have already completed in stream order) and resets
// the scalar accumulators (zero-invariant for graph replay).
// ---------------------------------------------------------------------------
__global__ void __launch_bounds__(256) k_restore(int s0, int n_u4, int do_final,
                                                 float* __restrict__ out) {
    uint4* p = reinterpret_cast<uint4*>(&g_rep[s0][0][0]);
    const uint4 z = make_uint4(0u, 0u, 0u, 0u);
    const int stride = gridDim.x * blockDim.x;
    for (int j = blockIdx.x * blockDim.x + threadIdx.x; j < n_u4; j += stride)
        p[j] = z;

    if (do_final && blockIdx.x == 0 && threadIdx.x == 0) {
        float np = (float)g_npos;
        float tot = 0.f;
        #pragma unroll
        for (int i = 0; i < NSC; i++) {
            float lm = logf(__uint_as_float(g_max[i]));
            float nzf = (float)g_nzero[i];
            tot += ((np - nzf) * lm - g_sumlog[i] + 100.f * nzf) / np;
            g_sumlog[i] = 0.f; g_max[i] = 0u; g_nzero[i] = 0u;
        }
        g_npos = 0u;
        out[0] = tot;
    }
}

// ---------------------------------------------------------------------------
// Launch: two scale-groups, each scatter -> stats -> restore, so the replica
// working set (68 MB / 51 MB) stays L2-resident through its whole pipeline.
// ---------------------------------------------------------------------------
extern "C" void kernel_launch(void* const* d_in, const int* in_sizes, int n_in,
                              void* d_out, int out_size) {
    const float4* r3 = (const float4*)d_in[0];
    const float4* c3 = (const float4*)d_in[1];
    const float4* r4 = (const float4*)d_in[2];
    const float4* c4 = (const float4*)d_in[3];
    const float*  target = (const float*)d_in[4];
    float* out = (float*)d_out;

    // Group A: scales 0..3 (68 MB replicas)
    {
        const int ns = 4;
        const int npts4 = ns * (MAPSZ / 4);
        k_scatter<<<npts4 / 256, 256>>>(r3, c3, r4, c4, 0, npts4);
        k_stats<<<ns * 1024, 256>>>(target, 0);
        k_restore<<<2048, 256>>>(0, ns * SC_U4, 0, out);
    }
    // Group B: scales 4..6 (51 MB replicas); restore-B computes the final.
    {
        const int ns = 3;
        const int npts4 = ns * (MAPSZ / 4);
        k_scatter<<<npts4 / 256, 256>>>(r3, c3, r4, c4, 4, npts4);
        k_stats<<<ns * 1024, 256>>>(target, 4);
        k_restore<<<2048, 256>>>(4, ns * SC_U4, 1, out);
    }
}

// round 11
// speedup vs baseline: 1.0734x; 1.0734x over previous
#include <cuda_runtime.h>
#include <cuda_fp16.h>
#include <math.h>

#define NSC 7
#define NB 8
#define ADIM 512
#define MAPSZ (NB * ADIM * ADIM)       // 2,097,152 cells per scale
#define PTS (NSC * MAPSZ)              // 14,680,064 points per coord set
#define TTY 258                        // tile-row stride (even for uint4)
#define TTX 257                        // tile rows
#define MAPH (TTX * TTY)               // 66306 tiles (8B each) per (map, replica)

// Scratch: 4 shift-replicas per scale; each 2x2 logical tile = 4 x f16 = uint2.
// ~119 MB. INVARIANT: all-zero at entry to every kernel_launch call
// (__device__ globals zero-init at load; k_stats/k_sweep re-zero after use).
__device__ __align__(16) uint2 g_rep[NSC][4][NB * MAPH];
__device__ float        g_sumlog[NSC];
__device__ unsigned int g_max[NSC];     // float bits (values >= 0)
__device__ unsigned int g_nzero[NSC];
__device__ unsigned int g_npos;

// ---------------------------------------------------------------------------
// K1: bilinear scatter, ALL scales — ONE red.global.add.noftz.v2.f16x2 per
// point. Replica (sx,sy) stores logical (x,y) at (x+sx, y+sy); sx=ixf&1,
// sy=iyf&1 puts the 2x2 footprint in exactly one aligned tile.
// Tile halves [0..3] = (dx,dy) = (0,0),(0,1),(1,0),(1,1).
// (Rate is LTS atomic-op bound: ~0.5 op/cyc/LTS — R10 falsified residency.)
// ---------------------------------------------------------------------------
__device__ __forceinline__ void scat1(int s, int b, float r, float c) {
    float xf = fminf(fmaxf(floorf(r), 0.f), 511.f);
    float yf = fminf(fmaxf(floorf(c), 0.f), 511.f);
    float xw = r - xf;
    float yw = c - yf;
    int ix = (int)xf, iy = (int)yf;
    int sx = ix & 1, sy = iy & 1;
    uint2* a = &g_rep[s][sx * 2 + sy][b * MAPH + ((ix + sx) >> 1) * TTY + ((iy + sy) >> 1)];
    float wx0 = 1.f - xw, wy0 = 1.f - yw;
    __half2 lo = __floats2half2_rn(wx0 * wy0, wx0 * yw);   // (0,0),(0,1)
    __half2 hi = __floats2half2_rn(xw * wy0,  xw * yw);    // (1,0),(1,1)
    unsigned ulo = *reinterpret_cast<unsigned*>(&lo);
    unsigned uhi = *reinterpret_cast<unsigned*>(&hi);
    asm volatile("red.global.add.noftz.v2.f16x2 [%0], {%1, %2};"
                 :: "l"(a), "r"(ulo), "r"(uhi)
                 : "memory");
}

__global__ void __launch_bounds__(256) k_scatter(
        const float4* __restrict__ r3, const float4* __restrict__ c3,
        const float4* __restrict__ r4, const float4* __restrict__ c4) {
    int i = blockIdx.x * blockDim.x + threadIdx.x;   // [0, PTS/4)
    if (i >= PTS / 4) return;
    int s = i >> 19;                                 // scale (MAPSZ/4 = 2^19)
    int b = (i >> 16) & 7;                           // batch within scale

    float4 rA = r3[i], cA = c3[i];
    float4 rB = r4[i], cB = c4[i];
    scat1(s, b, rA.x, cA.x); scat1(s, b, rA.y, cA.y);
    scat1(s, b, rA.z, cA.z); scat1(s, b, rA.w, cA.w);
    scat1(s, b, rB.x, cB.x); scat1(s, b, rB.y, cB.y);
    scat1(s, b, rB.z, cB.z); scat1(s, b, rB.w, cB.w);
}

// ---------------------------------------------------------------------------
// K2: fused combine + max + masked log-stats + INTERIOR restore-to-zero.
// CTA = 8x32 threads over (bx in block-of-8, byp in block-of-32). All
// cross-thread tile reads (+1/+2 col, +TTY row, corner) stay inside the CTA
// except at ty==0 rows / tx==0 cols of NEIGHBOR blocks — which are never
// zeroed here (k_sweep gets them). So zeroing own home uint4s after
// __syncthreads is race-free across the grid.
// BCE algebra: sum_{mask} min(lm - log(dm), 100)
//   = (npos - nzero)*lm - sum_{mask,dm>0} log(dm) + 100*nzero
// ---------------------------------------------------------------------------
__device__ __forceinline__ float lohalf(unsigned u) { return __half2float(__ushort_as_half((unsigned short)(u & 0xFFFF))); }
__device__ __forceinline__ float hihalf(unsigned u) { return __half2float(__ushort_as_half((unsigned short)(u >> 16))); }

__device__ __forceinline__ void stat_cell(float d, float t, float& sl,
                                          unsigned& nz, unsigned& np) {
    if (t == 1.0f) {
        np++;
        if (d == 0.f) nz++;
        else sl += __logf(d);
    }
}

__global__ void __launch_bounds__(256) k_stats(const float* __restrict__ target) {
    // blockIdx.x in [0, 7168): s | b | bxblk(32) | bypblk(4)
    const int s      = blockIdx.x >> 10;
    const int rem    = blockIdx.x & 1023;
    const int b      = rem >> 7;
    const int bxblk  = (rem >> 2) & 31;
    const int bypblk = rem & 3;
    const int tx = threadIdx.x & 31;     // byp within block
    const int ty = threadIdx.x >> 5;     // bx within block
    const int bx  = bxblk * 8 + ty;
    const int byp = bypblk * 32 + tx;
    const int by  = byp * 2;
    const int t00 = b * MAPH + bx * TTY + by;    // 16B aligned (TTY, by even)

    uint2* __restrict__ w00 = g_rep[s][0];
    uint2* __restrict__ w01 = g_rep[s][1];
    uint2* __restrict__ w10 = g_rep[s][2];
    uint2* __restrict__ w11 = g_rep[s][3];

    float mx, sl = 0.f;
    unsigned nz = 0, np = 0;
    {
        uint4 A  = *(const uint4*)(w00 + t00);
        uint4 B0 = *(const uint4*)(w01 + t00);
        uint2 B2 = w01[t00 + 2];
        uint4 C0 = *(const uint4*)(w10 + t00);
        uint4 C1 = *(const uint4*)(w10 + t00 + TTY);
        uint4 D0 = *(const uint4*)(w11 + t00);
        uint2 D2 = w11[t00 + 2];
        uint4 D1 = *(const uint4*)(w11 + t00 + TTY);
        uint2 D3 = w11[t00 + TTY + 2];

        // home tile 0: logical block (bx, by)
        float a00 = lohalf(A.x) + hihalf(B0.x) + lohalf(C0.y) + hihalf(D0.y);
        float a01 = hihalf(A.x) + lohalf(B0.z) + hihalf(C0.y) + lohalf(D0.w);
        float a10 = lohalf(A.y) + hihalf(B0.y) + lohalf(C1.x) + hihalf(D1.x);
        float a11 = hihalf(A.y) + lohalf(B0.w) + hihalf(C1.x) + lohalf(D1.z);
        // home tile 1: logical block (bx, by+1)
        float e00 = lohalf(A.z) + hihalf(B0.z) + lohalf(C0.w) + hihalf(D0.w);
        float e01 = hihalf(A.z) + lohalf(B2.x) + hihalf(C0.w) + lohalf(D2.y);
        float e10 = lohalf(A.w) + hihalf(B0.w) + lohalf(C1.z) + hihalf(D1.z);
        float e11 = hihalf(A.w) + lohalf(B2.y) + hihalf(C1.z) + lohalf(D3.x);

        mx = fmaxf(fmaxf(fmaxf(a00, a01), fmaxf(a10, a11)),
                   fmaxf(fmaxf(e00, e01), fmaxf(e10, e11)));

        const float* tp = target + b * (ADIM * ADIM) + (2 * bx) * ADIM + 2 * by;
        float4 t0 = *(const float4*)tp;
        float4 t1 = *(const float4*)(tp + ADIM);
        stat_cell(a00, t0.x, sl, nz, np);
        stat_cell(a01, t0.y, sl, nz, np);
        stat_cell(e00, t0.z, sl, nz, np);
        stat_cell(e01, t0.w, sl, nz, np);
        stat_cell(a10, t1.x, sl, nz, np);
        stat_cell(a11, t1.y, sl, nz, np);
        stat_cell(e10, t1.z, sl, nz, np);
        stat_cell(e11, t1.w, sl, nz, np);
    }
    #pragma unroll
    for (int o = 16; o; o >>= 1) {
        mx = fmaxf(mx, __shfl_xor_sync(0xFFFFFFFFu, mx, o));
        sl += __shfl_xor_sync(0xFFFFFFFFu, sl, o);
        nz += __shfl_xor_sync(0xFFFFFFFFu, nz, o);
        np += __shfl_xor_sync(0xFFFFFFFFu, np, o);
    }
    __shared__ float    smx[8], ssl[8];
    __shared__ unsigned snz[8], snp[8];
    int w = threadIdx.x >> 5;
    if ((threadIdx.x & 31) == 0) { smx[w] = mx; ssl[w] = sl; snz[w] = nz; snp[w] = np; }
    __syncthreads();   // also orders: ALL loads above complete before zeroing

    // Interior restore: zero own home uint4 in all 4 replicas. ty==0 / tx==0
    // tiles are read by neighbor CTAs -> left for k_sweep.
    if (ty != 0 && tx != 0) {
        const uint4 z = make_uint4(0u, 0u, 0u, 0u);
        *(uint4*)(w00 + t00) = z;
        *(uint4*)(w01 + t00) = z;
        *(uint4*)(w10 + t00) = z;
        *(uint4*)(w11 + t00) = z;
    }

    if (threadIdx.x == 0) {
        float bmx = smx[0], bsl = ssl[0];
        unsigned bnz = snz[0], bnp = snp[0];
        #pragma unroll
        for (int k = 1; k < 8; k++) {
            bmx = fmaxf(bmx, smx[k]); bsl += ssl[k]; bnz += snz[k]; bnp += snp[k];
        }
        atomicMax(&g_max[s], __float_as_uint(bmx));
        atomicAdd(&g_sumlog[s], bsl);
        if (bnz) atomicAdd(&g_nzero[s], bnz);
        if (s == 0) atomicAdd(&g_npos, bnp);
    }
}

// ---------------------------------------------------------------------------
// K3: sweep — zero the boundary tiles k_stats skipped (tile rows r % 8 == 0
// plus row 256; tile col pairs {0,1}+{64k,64k+1}+{256,257}), for all 224
// (scale,replica,map) planes. ~20 MB. Block 0 also computes the final loss
// (stats kernel already completed in stream order) and resets accumulators.
// ---------------------------------------------------------------------------
#define RM   (NSC * 4 * NB)            // 224 planes
#define ROWI (33 * 129)                // row part: 33 rows x 129 uint4
#define COLI (5 * 257)                 // col part: 5 uint4-cols x 257 rows
#define SWI  (ROWI + COLI)             // 5542 uint4 per plane

__global__ void __launch_bounds__(256) k_sweep(float* __restrict__ out) {
    int gid = blockIdx.x * blockDim.x + threadIdx.x;
    if (gid < RM * SWI) {
        int rm   = gid / SWI;
        int rest = gid - rm * SWI;
        int r, c;
        if (rest < ROWI) {           // full rows 0,8,...,256
            int rr = rest / 129;
            r = rr * 8;
            c = (rest - rr * 129) * 2;
        } else {                     // cols {0,64,128,192,256} (uint4 pairs)
            int t = rest - ROWI;
            int ci = t / 257;
            c = ci * 64;
            r = t - ci * 257;
        }
        uint2* base = &g_rep[0][0][0] + (size_t)rm * MAPH;
        *(uint4*)(base + r * TTY + c) = make_uint4(0u, 0u, 0u, 0u);
    }
    if (blockIdx.x == 0 && threadIdx.x == 0) {
        float np = (float)g_npos;
        float tot = 0.f;
        #pragma unroll
        for (int i = 0; i < NSC; i++) {
            float lm = logf(__uint_as_float(g_max[i]));
            float nzf = (float)g_nzero[i];
            tot += ((np - nzf) * lm - g_sumlog[i] + 100.f * nzf) / np;
            g_sumlog[i] = 0.f; g_max[i] = 0u; g_nzero[i] = 0u;
        }
        g_npos = 0u;
        out[0] = tot;
    }
}

// ---------------------------------------------------------------------------
// Launch: single stream, 3 nodes: scatter -> stats(+interior restore) -> sweep(+final)
// ---------------------------------------------------------------------------
extern "C" void kernel_launch(void* const* d_in, const int* in_sizes, int n_in,
                              void* d_out, int out_size) {
    const float4* r3 = (const float4*)d_in[0];
    const float4* c3 = (const float4*)d_in[1];
    const float4* r4 = (const float4*)d_in[2];
    const float4* c4 = (const float4*)d_in[3];
    const float*  target = (const float*)d_in[4];
    float* out = (float*)d_out;

    k_scatter<<<PTS / 4 / 256, 256>>>(r3, c3, r4, c4);     // 14336 CTAs
    k_stats<<<NSC * 1024, 256>>>(target);                  // 7168 CTAs
    k_sweep<<<(RM * SWI + 255) / 256, 256>>>(out);         // 4850 CTAs
}